// round 13
// baseline (speedup 1.0000x reference)
#include <cuda_runtime.h>
#include <math.h>
#include <stdint.h>

// B=64 batches, per batch N=Q*C=400000 fp32 logits.
// Output f32 concat: scores[B*K] | labels[B*K] | segments[B*K*2] | query_ids[B*K].
//
// Single fused kernel, grid (SLICES, B) = (8, 64) = 512 CTAs, 288 threads:
// DUAL-ENGINE streaming. Warps 0-7 (256 thr) stream ~60% of the CTA slice
// via the per-thread cp.async DEPTH=8 ring (the proven 35us path). Warp 8
// concurrently streams the remaining ~40% via its own 3 x 8KB TMA bulk ring
// (single-warp: slot free == scan done, no cross-warp sync). SM-request
// tracking (LDGSTS) and TMA-unit tracking are separate; if independent,
// bandwidths add. Hits (logit > 2.8, superset of top-100 for N(0,1) data,
// ~28-sigma margin) staged in smem, flushed to per-batch candidate buffer.
// Last-arriving slice CTA per batch: exact MSD radix-select over the ~1k
// candidates (cached in freed pipe smem), rank K winners, emit outputs,
// reset counters. Exact full-scan fallback if the candidate set is unusable.

#define MAXB    64
#define CAP     16384
#define SLICES  8
#define TPB     288                 // 8 cp.async warps + 1 TMA warp
#define CPT     256                 // cp.async threads
#define KMAX    128
#define SBUF    384
#define DEPTH   8
#define NST     3                   // TMA ring stages
#define TILE_F  2048                // floats per TMA tile (8 KB)
#define TILE_B  (TILE_F * 4)

#define RING_OFF   0
#define RING_BYTES (DEPTH * CPT * 16)               // 32768
#define TMA_OFF    RING_BYTES                       // 32768
#define TMA_BYTES  (NST * TILE_B)                   // 24576
#define MBAR_OFF   (TMA_OFF + TMA_BYTES)            // 57344
#define SVAL_OFF   (MBAR_OFF + NST * 8 + 8)         // 57376 (16-aligned)
#define SIDX_OFF   (SVAL_OFF + SBUF * 4)
#define SMEM_BYTES (SIDX_OFF + SBUF * 4 + 16)
#define SELCACHE   ((RING_BYTES + TMA_BYTES) / 8)   // 7168 u64 slots

__device__ unsigned long long g_cand[MAXB * CAP];
__device__ int g_cnt[MAXB];
__device__ int g_done[MAXB];

__device__ __forceinline__ unsigned long long make_key(float x, unsigned idx) {
    float s = 1.0f / (1.0f + expf(-x));   // sigmoid ordering == jax (rel_err 8e-9 verified)
    return ((unsigned long long)__float_as_uint(s) << 32) | (unsigned long long)(~idx);
}

__device__ __forceinline__ float max4(float4 v) {
    return fmaxf(fmaxf(v.x, v.y), fmaxf(v.z, v.w));
}

__device__ __forceinline__ uint32_t smem_u32(const void* p) {
    uint32_t a;
    asm("{ .reg .u64 t; cvta.to.shared.u64 t, %1; cvt.u32.u64 %0, t; }" : "=r"(a) : "l"(p));
    return a;
}

__device__ __forceinline__ void cp_async16(uint32_t dst, const float4* src) {
    asm volatile("cp.async.cg.shared.global [%0], [%1], 16;"
                 :: "r"(dst), "l"(src) : "memory");
}
__device__ __forceinline__ void cp_commit() {
    asm volatile("cp.async.commit_group;" ::: "memory");
}
__device__ __forceinline__ void cp_wait_most() {       // allow DEPTH-1 outstanding
    asm volatile("cp.async.wait_group %0;" :: "n"(DEPTH - 1) : "memory");
}
__device__ __forceinline__ void cp_wait_all() {
    asm volatile("cp.async.wait_all;" ::: "memory");
}

__device__ __forceinline__ void mbar_init(uint32_t mbar, uint32_t count) {
    asm volatile("mbarrier.init.shared.b64 [%0], %1;" :: "r"(mbar), "r"(count) : "memory");
}
__device__ __forceinline__ void mbar_wait(uint32_t mbar, uint32_t parity) {
    asm volatile(
        "{\n\t.reg .pred P;\n"
        "W_%=:\n\t"
        "mbarrier.try_wait.parity.acquire.cta.shared::cta.b64 P, [%0], %1, 0x989680;\n\t"
        "@!P bra W_%=;\n\t}"
        :: "r"(mbar), "r"(parity) : "memory");
}
__device__ __forceinline__ void tma_issue(uint32_t dst, const float* src, uint32_t bytes,
                                          uint32_t mbar) {
    asm volatile("mbarrier.arrive.expect_tx.shared.b64 _, [%0], %1;"
                 :: "r"(mbar), "r"(bytes) : "memory");
    asm volatile("cp.async.bulk.shared::cluster.global.mbarrier::complete_tx::bytes "
                 "[%0], [%1], %2, [%3];"
                 :: "r"(dst), "l"(src), "r"(bytes), "r"(mbar) : "memory");
}

// ---- exact top-K selection over candidates (or full logits on fallback) ----
__device__ void do_select(const float* __restrict__ lg,
                          const float* __restrict__ segs,
                          const float* __restrict__ ts,
                          float* __restrict__ out,
                          unsigned long long* s_cache,
                          int b, int B, int Q, int C, int K, int N) {
    int tid = threadIdx.x;
    int lane = tid & 31;
    int wid = tid >> 5;

    int cnt = g_cnt[b];
    bool slow = (cnt < K) || (cnt > CAP);
    int M = slow ? N : cnt;
    const unsigned long long* cand = g_cand + (long long)b * CAP;

    bool cached = (!slow) && (M <= SELCACHE);   // pipe smem is free now
    if (cached) {
        for (int i = tid; i < M; i += TPB) s_cache[i] = cand[i];
    }
    __shared__ int hist[256];
    __shared__ int wtot[9];
    __shared__ unsigned long long sh_prefix;
    __shared__ int sh_remaining;
    if (tid == 0) { sh_prefix = 0ULL; sh_remaining = K; }
    __syncthreads();

    for (int d = 7; d >= 0; --d) {
        if (tid < 256) hist[tid] = 0;
        __syncthreads();
        int shift = d * 8;
        unsigned long long pmask = (d == 7) ? 0ULL : (~0ULL << (shift + 8));
        unsigned long long prefix = sh_prefix;
        for (int i = tid; i < M; i += TPB) {
            unsigned long long key = cached ? s_cache[i]
                                   : (slow ? make_key(lg[i], (unsigned)i) : cand[i]);
            if ((key & pmask) == prefix)
                atomicAdd(&hist[(int)((key >> shift) & 255)], 1);
        }
        __syncthreads();
        if (tid < 256) {
            int rem = sh_remaining;
            int h = hist[tid];
            int x = h;                      // suffix-scan within warp
            #pragma unroll
            for (int off = 1; off < 32; off <<= 1) {
                int y = __shfl_down_sync(0xffffffffu, x, off);
                if (lane + off < 32) x += y;
            }
            if (lane == 0) wtot[wid] = x;
            __syncthreads();
            int wsum = 0;
            #pragma unroll
            for (int w = 0; w < 8; w++) if (w > wid) wsum += wtot[w];
            int suffix = x + wsum;          // sum of hist[tid..255]
            if (suffix >= rem && (suffix - h) < rem) {   // unique chosen bin
                sh_prefix = prefix | ((unsigned long long)tid << shift);
                sh_remaining = rem - (suffix - h);
            }
        } else {
            __syncthreads();
        }
        __syncthreads();
    }
    unsigned long long kth = sh_prefix;   // exact K-th largest key (keys unique)

    __shared__ unsigned long long win[KMAX];
    __shared__ int wc;
    if (tid == 0) wc = 0;
    __syncthreads();
    for (int i = tid; i < M; i += TPB) {
        unsigned long long key = cached ? s_cache[i]
                               : (slow ? make_key(lg[i], (unsigned)i) : cand[i]);
        if (key >= kth) {
            int p = atomicAdd(&wc, 1);
            if (p < KMAX) win[p] = key;
        }
    }
    __syncthreads();

    if (tid < K) {
        unsigned long long k0 = win[tid];
        int rank = 0;
        for (int j = 0; j < K; j++) rank += (win[j] > k0);
        float score = __uint_as_float((unsigned)(k0 >> 32));
        unsigned idx = ~(unsigned)(k0 & 0xffffffffu);
        int q = (int)(idx / (unsigned)C);
        int lbl = (int)(idx - (unsigned)q * (unsigned)C);
        float c = segs[((long long)b * Q + q) * 2 + 0];
        float w = segs[((long long)b * Q + q) * 2 + 1];
        float t = ts[b];
        int BK = B * K;
        int o = b * K + rank;
        out[o]                  = score;
        out[BK + o]             = (float)lbl;
        out[2 * BK + 2 * o]     = (c - 0.5f * w) * t;
        out[2 * BK + 2 * o + 1] = (c + 0.5f * w) * t;
        out[4 * BK + o]         = (float)q;
    }
    __syncthreads();
    if (tid == 0) { g_done[b] = 0; g_cnt[b] = 0; }   // reset for next graph replay
}

__global__ void __launch_bounds__(TPB)
k_main(const float* __restrict__ logits,
       const float* __restrict__ segs,
       const float* __restrict__ ts,
       float* __restrict__ out,
       int B, int Q, int C, int K, int per_cta, float thresh) {
    extern __shared__ __align__(16) char dsm[];
    float4*   s_ring = (float4*)(dsm + RING_OFF);     // cp.async per-thread columns
    float*    s_tma  = (float*)(dsm + TMA_OFF);       // TMA tiles
    float*    s_val  = (float*)(dsm + SVAL_OFF);
    unsigned* s_idx  = (unsigned*)(dsm + SIDX_OFF);
    __shared__ int s_cnt;
    __shared__ int s_base;

    int b = blockIdx.y;
    int N = Q * C;
    int start = blockIdx.x * per_cta;
    int tid = threadIdx.x;
    int lane = tid & 31;

    uint32_t mbar_a = smem_u32(dsm + MBAR_OFF);
    uint32_t tma_a  = smem_u32(s_tma);

    if (tid == 0) s_cnt = 0;
    if (tid < NST) mbar_init(mbar_a + tid * 8, 1);
    __syncthreads();

    auto push_hit = [&](float x, unsigned idx) {
        int pos = atomicAdd(&s_cnt, 1);
        if (pos < SBUF) {
            s_val[pos] = x;
            s_idx[pos] = idx;
        } else {                                   // smem overflow: direct global (rare)
            int p = atomicAdd(&g_cnt[b], 1);
            if (p < CAP) g_cand[b * CAP + p] = make_key(x, idx);
        }
    };

    int count = (start < N) ? min(per_cta, N - start) : 0;
    const float* base = logits + (long long)b * N + start;
    int cp_n = ((count * 3) / 5) & ~3;               // cp.async portion (16B aligned)
    int tma_n = count - cp_n;                        // TMA portion

    if (tid < CPT) {
        // -------- warps 0-7: per-thread cp.async ring over [0, cp_n) --------
        if (cp_n > 0) {
            const float4* src = (const float4*)base;
            int n4 = cp_n >> 2;
            int iters = (n4 + CPT - 1) / CPT;
            uint32_t myslot0 = smem_u32(&s_ring[tid]);

            #pragma unroll
            for (int d = 0; d < DEPTH; d++) {        // prologue: fill ring
                int idx = d * CPT + tid;
                if (idx < n4) cp_async16(myslot0 + d * (CPT * 16), src + idx);
                cp_commit();
            }
            for (int k = 0; k < iters; k++) {
                cp_wait_most();                      // group k done -> slot k%DEPTH ready
                int s = k & (DEPTH - 1);
                int idx = k * CPT + tid;
                if (idx < n4) {
                    float4 v = s_ring[s * CPT + tid];
                    if (max4(v) > thresh) {
                        unsigned i0 = (unsigned)(start + 4 * idx);
                        if (v.x > thresh) push_hit(v.x, i0);
                        if (v.y > thresh) push_hit(v.y, i0 + 1);
                        if (v.z > thresh) push_hit(v.z, i0 + 2);
                        if (v.w > thresh) push_hit(v.w, i0 + 3);
                    }
                }
                int nidx = (k + DEPTH) * CPT + tid;  // refill consumed slot
                if (nidx < n4) cp_async16(myslot0 + s * (CPT * 16), src + nidx);
                cp_commit();
            }
            cp_wait_all();                           // ring smem idle before reuse
        }
    } else {
        // -------- warp 8: single-warp TMA bulk ring over [cp_n, count) --------
        const float* tbase = base + cp_n;
        int t4 = tma_n & ~3;
        int tiles = (t4 + TILE_F - 1) / TILE_F;

        if (lane == 0) {                             // prologue: fill 3-deep ring
            int pre = tiles < NST ? tiles : NST;
            for (int t = 0; t < pre; t++) {
                uint32_t bytes = (uint32_t)(min(TILE_F, t4 - t * TILE_F) * 4);
                tma_issue(tma_a + t * TILE_B, tbase + t * TILE_F, bytes, mbar_a + t * 8);
            }
        }
        int slot = 0, ph = 0;
        for (int t = 0; t < tiles; t++) {
            mbar_wait(mbar_a + slot * 8, (uint32_t)ph);
            int nf4 = min(TILE_F, t4 - t * TILE_F) >> 2;
            const float4* tp = (const float4*)(s_tma + slot * TILE_F);
            unsigned gb = (unsigned)(start + cp_n + t * TILE_F);
            #pragma unroll 4
            for (int j = lane; j < nf4; j += 32) {
                float4 v = tp[j];
                if (max4(v) > thresh) {
                    unsigned i0 = gb + 4 * j;
                    if (v.x > thresh) push_hit(v.x, i0);
                    if (v.y > thresh) push_hit(v.y, i0 + 1);
                    if (v.z > thresh) push_hit(v.z, i0 + 2);
                    if (v.w > thresh) push_hit(v.w, i0 + 3);
                }
            }
            __syncwarp();                            // slot consumed by whole warp
            int nt = t + NST;
            if (lane == 0 && nt < tiles) {
                uint32_t bytes = (uint32_t)(min(TILE_F, t4 - nt * TILE_F) * 4);
                tma_issue(tma_a + slot * TILE_B, tbase + nt * TILE_F, bytes, mbar_a + slot * 8);
            }
            if (++slot == NST) { slot = 0; ph ^= 1; }
        }
        // scalar tail (count % 4 != 0; never for this shape)
        int tl = tma_n - t4;
        if (lane < tl) {
            float x = tbase[t4 + lane];
            if (x > thresh) push_hit(x, (unsigned)(start + cp_n + t4 + lane));
        }
    }

    // ---- flush: convert staged (logit, idx) -> keys in global ----
    __syncthreads();
    int cnt = min(s_cnt, SBUF);
    if (tid == 0) s_base = atomicAdd(&g_cnt[b], cnt);
    __syncthreads();
    int bs = s_base;
    for (int i2 = tid; i2 < cnt; i2 += TPB) {
        int p = bs + i2;
        if (p < CAP) g_cand[b * CAP + p] = make_key(s_val[i2], s_idx[i2]);
    }

    // ---- arrival: last slice CTA of this batch performs the selection ----
    __threadfence();
    __syncthreads();
    __shared__ int is_last;
    if (tid == 0)
        is_last = (atomicAdd(&g_done[b], 1) == gridDim.x - 1);
    __syncthreads();
    if (is_last) {
        __threadfence();   // acquire: other CTAs' candidate stores visible
        do_select(logits + (long long)b * N, segs, ts, out,
                  (unsigned long long*)dsm, b, B, Q, C, K, N);
    }
}

extern "C" void kernel_launch(void* const* d_in, const int* in_sizes, int n_in,
                              void* d_out, int out_size) {
    const float* logits = (const float*)d_in[0];   // [B, Q, C] f32
    const float* segs   = (const float*)d_in[1];   // [B, Q, 2] f32
    const float* ts     = (const float*)d_in[2];   // [B] f32

    int B = in_sizes[2];
    int N = in_sizes[0] / B;          // Q * C
    int Q = in_sizes[1] / (2 * B);
    int C = N / Q;
    int K = 100;
    if (K > N) K = N;

    cudaFuncSetAttribute(k_main, cudaFuncAttributeMaxDynamicSharedMemorySize, SMEM_BYTES);

    int per_cta = (((N + SLICES - 1) / SLICES) + 3) & ~3;
    dim3 grid(SLICES, B);
    k_main<<<grid, TPB, SMEM_BYTES>>>(logits, segs, ts, (float*)d_out, B, Q, C, K, per_cta, 2.8f);
}

// round 14
// speedup vs baseline: 1.7700x; 1.7700x over previous
#include <cuda_runtime.h>
#include <math.h>
#include <stdint.h>

// B=64 batches, per batch N=Q*C=400000 fp32 logits.
// Output f32 concat: scores[B*K] | labels[B*K] | segments[B*K*2] | query_ids[B*K].
//
// Single fused kernel, grid (SLICES, B) = (16, 64) = 1024 CTAs, 256 threads:
//  - collect: DIRECT __ldcv (LDG.E.CV.128) streaming, 8 independent float4
//    loads per thread-iteration, no smem staging. LDG.cv is the instruction
//    measured to reach the ~6300 B/cyc LTS cap (vs cp.async's LDGSTS pipe,
//    rt=8 cyc/SMSP = the ~2.8 TB/s ceiling seen in R5/R9/R12).
//    Hits (logit > 2.8, superset of top-100 for N(0,1) data, ~28-sigma
//    margin) stash the whole float4 to smem (~1% of float4s), expanded
//    per-component (sigmoid) post-loop into a per-batch candidate buffer.
//  - last-arriving slice CTA per batch: exact MSD radix-select over the ~1k
//    candidates (cached in smem), rank K winners, emit outputs, reset
//    counters for the next graph replay.
//  - exact fallback over the full batch if the candidate set is unusable.

#define MAXB    64
#define CAP     16384
#define SLICES  16
#define TPB     256
#define KMAX    128
#define STASH   160
#define SELCACHE 2048     // u64 slots (16KB smem cache; candidate count ~1.1k)

__device__ unsigned long long g_cand[MAXB * CAP];
__device__ int g_cnt[MAXB];
__device__ int g_done[MAXB];

__device__ __forceinline__ unsigned long long make_key(float x, unsigned idx) {
    float s = 1.0f / (1.0f + expf(-x));   // sigmoid ordering == jax (rel_err 8e-9 verified)
    return ((unsigned long long)__float_as_uint(s) << 32) | (unsigned long long)(~idx);
}

__device__ __forceinline__ float max4(float4 v) {
    return fmaxf(fmaxf(v.x, v.y), fmaxf(v.z, v.w));
}

// ---- exact top-K selection over candidates (or full logits on fallback) ----
__device__ void do_select(const float* __restrict__ lg,
                          const float* __restrict__ segs,
                          const float* __restrict__ ts,
                          float* __restrict__ out,
                          unsigned long long* s_cache,
                          int b, int B, int Q, int C, int K, int N) {
    int tid = threadIdx.x;
    int lane = tid & 31;
    int wid = tid >> 5;

    int cnt = g_cnt[b];
    bool slow = (cnt < K) || (cnt > CAP);
    int M = slow ? N : cnt;
    const unsigned long long* cand = g_cand + (long long)b * CAP;

    bool cached = (!slow) && (M <= SELCACHE);
    if (cached) {
        for (int i = tid; i < M; i += TPB) s_cache[i] = cand[i];
    }
    __shared__ int hist[256];
    __shared__ int wtot[8];
    __shared__ unsigned long long sh_prefix;
    __shared__ int sh_remaining;
    if (tid == 0) { sh_prefix = 0ULL; sh_remaining = K; }
    __syncthreads();

    for (int d = 7; d >= 0; --d) {
        hist[tid] = 0;
        __syncthreads();
        int shift = d * 8;
        unsigned long long pmask = (d == 7) ? 0ULL : (~0ULL << (shift + 8));
        unsigned long long prefix = sh_prefix;
        for (int i = tid; i < M; i += TPB) {
            unsigned long long key = cached ? s_cache[i]
                                   : (slow ? make_key(lg[i], (unsigned)i) : cand[i]);
            if ((key & pmask) == prefix)
                atomicAdd(&hist[(int)((key >> shift) & 255)], 1);
        }
        __syncthreads();
        int rem = sh_remaining;
        int h = hist[tid];
        int x = h;                      // suffix-scan within warp
        #pragma unroll
        for (int off = 1; off < 32; off <<= 1) {
            int y = __shfl_down_sync(0xffffffffu, x, off);
            if (lane + off < 32) x += y;
        }
        if (lane == 0) wtot[wid] = x;
        __syncthreads();
        int wsum = 0;
        #pragma unroll
        for (int w = 0; w < 8; w++) if (w > wid) wsum += wtot[w];
        int suffix = x + wsum;          // sum of hist[tid..255]
        if (suffix >= rem && (suffix - h) < rem) {   // unique chosen bin
            sh_prefix = prefix | ((unsigned long long)tid << shift);
            sh_remaining = rem - (suffix - h);
        }
        __syncthreads();
    }
    unsigned long long kth = sh_prefix;   // exact K-th largest key (keys unique)

    __shared__ unsigned long long win[KMAX];
    __shared__ int wc;
    if (tid == 0) wc = 0;
    __syncthreads();
    for (int i = tid; i < M; i += TPB) {
        unsigned long long key = cached ? s_cache[i]
                               : (slow ? make_key(lg[i], (unsigned)i) : cand[i]);
        if (key >= kth) {
            int p = atomicAdd(&wc, 1);
            if (p < KMAX) win[p] = key;
        }
    }
    __syncthreads();

    if (tid < K) {
        unsigned long long k0 = win[tid];
        int rank = 0;
        for (int j = 0; j < K; j++) rank += (win[j] > k0);
        float score = __uint_as_float((unsigned)(k0 >> 32));
        unsigned idx = ~(unsigned)(k0 & 0xffffffffu);
        int q = (int)(idx / (unsigned)C);
        int lbl = (int)(idx - (unsigned)q * (unsigned)C);
        float c = segs[((long long)b * Q + q) * 2 + 0];
        float w = segs[((long long)b * Q + q) * 2 + 1];
        float t = ts[b];
        int BK = B * K;
        int o = b * K + rank;
        out[o]                  = score;
        out[BK + o]             = (float)lbl;
        out[2 * BK + 2 * o]     = (c - 0.5f * w) * t;
        out[2 * BK + 2 * o + 1] = (c + 0.5f * w) * t;
        out[4 * BK + o]         = (float)q;
    }
    __syncthreads();
    if (tid == 0) { g_done[b] = 0; g_cnt[b] = 0; }   // reset for next graph replay
}

__global__ void __launch_bounds__(TPB, 4)
k_main(const float* __restrict__ logits,
       const float* __restrict__ segs,
       const float* __restrict__ ts,
       float* __restrict__ out,
       int B, int Q, int C, int K, int per_cta, float thresh) {
    int b = blockIdx.y;
    int N = Q * C;
    int start = blockIdx.x * per_cta;
    int tid = threadIdx.x;

    __shared__ unsigned long long s_cache[SELCACHE];      // select cache (16KB)
    __shared__ __align__(16) float4 s_v4[STASH];          // stashed hit vectors
    __shared__ unsigned s_i[STASH];
    __shared__ int s_cnt;

    if (tid == 0) s_cnt = 0;
    __syncthreads();

    // stash a whole float4 (rare: ~1% of float4s); overflow -> direct global
    auto stash_vec = [&](float4 v, unsigned i0) {
        int pos = atomicAdd(&s_cnt, 1);
        if (pos < STASH) {
            s_v4[pos] = v;
            s_i[pos] = i0;
        } else {
            if (v.x > thresh) { int g = atomicAdd(&g_cnt[b], 1); if (g < CAP) g_cand[b * CAP + g] = make_key(v.x, i0); }
            if (v.y > thresh) { int g = atomicAdd(&g_cnt[b], 1); if (g < CAP) g_cand[b * CAP + g] = make_key(v.y, i0 + 1); }
            if (v.z > thresh) { int g = atomicAdd(&g_cnt[b], 1); if (g < CAP) g_cand[b * CAP + g] = make_key(v.z, i0 + 2); }
            if (v.w > thresh) { int g = atomicAdd(&g_cnt[b], 1); if (g < CAP) g_cand[b * CAP + g] = make_key(v.w, i0 + 3); }
        }
    };

    if (start < N) {
        int count = min(per_cta, N - start);
        const float* base = logits + (long long)b * N + start;
        const float4* src = (const float4*)base;   // start is a multiple of 4 floats
        int n4 = count >> 2;

        int i = tid;
        // main loop: 8 independent LDG.E.CV.128 per iteration (L1-bypass path)
        for (; i + 7 * TPB < n4; i += 8 * TPB) {
            float4 a0 = __ldcv(src + i);
            float4 a1 = __ldcv(src + i + TPB);
            float4 a2 = __ldcv(src + i + 2 * TPB);
            float4 a3 = __ldcv(src + i + 3 * TPB);
            float4 a4 = __ldcv(src + i + 4 * TPB);
            float4 a5 = __ldcv(src + i + 5 * TPB);
            float4 a6 = __ldcv(src + i + 6 * TPB);
            float4 a7 = __ldcv(src + i + 7 * TPB);
            float m = fmaxf(fmaxf(fmaxf(max4(a0), max4(a1)), fmaxf(max4(a2), max4(a3))),
                            fmaxf(fmaxf(max4(a4), max4(a5)), fmaxf(max4(a6), max4(a7))));
            if (m > thresh) {                      // ~8% per thread-iteration
                unsigned i0 = (unsigned)(start + 4 * i);
                if (max4(a0) > thresh) stash_vec(a0, i0);
                if (max4(a1) > thresh) stash_vec(a1, i0 + 4 * TPB);
                if (max4(a2) > thresh) stash_vec(a2, i0 + 8 * TPB);
                if (max4(a3) > thresh) stash_vec(a3, i0 + 12 * TPB);
                if (max4(a4) > thresh) stash_vec(a4, i0 + 16 * TPB);
                if (max4(a5) > thresh) stash_vec(a5, i0 + 20 * TPB);
                if (max4(a6) > thresh) stash_vec(a6, i0 + 24 * TPB);
                if (max4(a7) > thresh) stash_vec(a7, i0 + 28 * TPB);
            }
        }
        // singles remainder
        for (; i < n4; i += TPB) {
            float4 a0 = __ldcv(src + i);
            if (max4(a0) > thresh) stash_vec(a0, (unsigned)(start + 4 * i));
        }
        // scalar tail (only if count % 4 != 0; never for this shape)
        int cnt4 = n4 << 2;
        int tail = count - cnt4;
        if (tid < tail) {
            float x = base[cnt4 + tid];
            if (x > thresh) {
                int g = atomicAdd(&g_cnt[b], 1);
                if (g < CAP) g_cand[b * CAP + g] = make_key(x, (unsigned)(start + cnt4 + tid));
            }
        }
    }

    // ---- expand stashed vectors -> per-component keys in global ----
    __syncthreads();
    int sc = min(s_cnt, STASH);
    for (int i = tid; i < sc; i += TPB) {
        float4 v = s_v4[i];
        unsigned i0 = s_i[i];
        if (v.x > thresh) { int g = atomicAdd(&g_cnt[b], 1); if (g < CAP) g_cand[b * CAP + g] = make_key(v.x, i0); }
        if (v.y > thresh) { int g = atomicAdd(&g_cnt[b], 1); if (g < CAP) g_cand[b * CAP + g] = make_key(v.y, i0 + 1); }
        if (v.z > thresh) { int g = atomicAdd(&g_cnt[b], 1); if (g < CAP) g_cand[b * CAP + g] = make_key(v.z, i0 + 2); }
        if (v.w > thresh) { int g = atomicAdd(&g_cnt[b], 1); if (g < CAP) g_cand[b * CAP + g] = make_key(v.w, i0 + 3); }
    }

    // ---- arrival: last slice CTA of this batch performs the selection ----
    __threadfence();
    __syncthreads();
    __shared__ int is_last;
    if (tid == 0)
        is_last = (atomicAdd(&g_done[b], 1) == gridDim.x - 1);
    __syncthreads();
    if (is_last) {
        __threadfence();   // acquire: other CTAs' candidate stores visible
        do_select(logits + (long long)b * N, segs, ts, out,
                  s_cache, b, B, Q, C, K, N);
    }
}

extern "C" void kernel_launch(void* const* d_in, const int* in_sizes, int n_in,
                              void* d_out, int out_size) {
    const float* logits = (const float*)d_in[0];   // [B, Q, C] f32
    const float* segs   = (const float*)d_in[1];   // [B, Q, 2] f32
    const float* ts     = (const float*)d_in[2];   // [B] f32

    int B = in_sizes[2];
    int N = in_sizes[0] / B;          // Q * C
    int Q = in_sizes[1] / (2 * B);
    int C = N / Q;
    int K = 100;
    if (K > N) K = N;

    int per_cta = (((N + SLICES - 1) / SLICES) + 3) & ~3;
    dim3 grid(SLICES, B);
    k_main<<<grid, TPB>>>(logits, segs, ts, (float*)d_out, B, Q, C, K, per_cta, 2.8f);
}

// round 15
// speedup vs baseline: 2.1429x; 1.2106x over previous
#include <cuda_runtime.h>
#include <math.h>
#include <stdint.h>

// B=64 batches, per batch N=Q*C=400000 fp32 logits.
// Output f32 concat: scores[B*K] | labels[B*K] | segments[B*K*2] | query_ids[B*K].
//
// Single fused kernel, grid (SLICES, B) = (8, 64) = 512 CTAs. This is the
// R12 best configuration (34.98us) unchanged except threshold 2.8 -> 3.0,
// which halves the candidate set (E[count] ~540/batch, 19-sigma above K=100;
// the exact full-scan fallback keeps correctness unconditional) and trims
// the flush + radix-select tail. Streaming BW is at the measured platform
// floor (~2.8 TB/s across LDG/LDG.cv/LDGSTS/TMA in R1-R14).
//
//  - collect: per-thread cp.async (LDGSTS) ring, DEPTH=8 x 16B slots, with
//    L2::evict_last hints. Hits staged in smem, bulk-flushed per batch.
//  - last-arriving slice CTA per batch: exact MSD radix-select over the
//    candidates (cached in the freed pipe smem), rank K winners, emit
//    outputs, reset counters for the next graph replay.
//  - exact fallback over the full batch if the candidate set is unusable.

#define MAXB    64
#define CAP     16384
#define SLICES  8
#define TPB     256
#define KMAX    128
#define SBUF    384
#define DEPTH   8
#define SELCACHE 4096     // u64 slots available in pipe smem (32KB)

__device__ unsigned long long g_cand[MAXB * CAP];
__device__ int g_cnt[MAXB];
__device__ int g_done[MAXB];

__device__ __forceinline__ unsigned long long make_key(float x, unsigned idx) {
    float s = 1.0f / (1.0f + expf(-x));   // sigmoid ordering == jax (rel_err 8e-9 verified)
    return ((unsigned long long)__float_as_uint(s) << 32) | (unsigned long long)(~idx);
}

__device__ __forceinline__ float max4(float4 v) {
    return fmaxf(fmaxf(v.x, v.y), fmaxf(v.z, v.w));
}

__device__ __forceinline__ uint32_t smem_u32(const void* p) {
    uint32_t a;
    asm("{ .reg .u64 t; cvta.to.shared.u64 t, %1; cvt.u32.u64 %0, t; }" : "=r"(a) : "l"(p));
    return a;
}

__device__ __forceinline__ uint64_t l2_keep_policy() {
    uint64_t p;
    asm("createpolicy.fractional.L2::evict_last.b64 %0, 1.0;" : "=l"(p));
    return p;
}

__device__ __forceinline__ void cp_async16(uint32_t dst, const float4* src, uint64_t pol) {
    asm volatile("cp.async.cg.shared.global.L2::cache_hint [%0], [%1], 16, %2;"
                 :: "r"(dst), "l"(src), "l"(pol) : "memory");
}
__device__ __forceinline__ void cp_commit() {
    asm volatile("cp.async.commit_group;" ::: "memory");
}
__device__ __forceinline__ void cp_wait_most() {       // allow DEPTH-1 outstanding
    asm volatile("cp.async.wait_group %0;" :: "n"(DEPTH - 1) : "memory");
}
__device__ __forceinline__ void cp_wait_all() {
    asm volatile("cp.async.wait_all;" ::: "memory");
}

// ---- exact top-K selection over candidates (or full logits on fallback) ----
__device__ void do_select(const float* __restrict__ lg,
                          const float* __restrict__ segs,
                          const float* __restrict__ ts,
                          float* __restrict__ out,
                          unsigned long long* s_cache,
                          int b, int B, int Q, int C, int K, int N) {
    int tid = threadIdx.x;
    int lane = tid & 31;
    int wid = tid >> 5;

    int cnt = g_cnt[b];
    bool slow = (cnt < K) || (cnt > CAP);
    int M = slow ? N : cnt;
    const unsigned long long* cand = g_cand + (long long)b * CAP;

    bool cached = (!slow) && (M <= SELCACHE);   // pipe smem is free now
    if (cached) {
        for (int i = tid; i < M; i += TPB) s_cache[i] = cand[i];
    }
    __shared__ int hist[256];
    __shared__ int wtot[8];
    __shared__ unsigned long long sh_prefix;
    __shared__ int sh_remaining;
    if (tid == 0) { sh_prefix = 0ULL; sh_remaining = K; }
    __syncthreads();

    for (int d = 7; d >= 0; --d) {
        hist[tid] = 0;
        __syncthreads();
        int shift = d * 8;
        unsigned long long pmask = (d == 7) ? 0ULL : (~0ULL << (shift + 8));
        unsigned long long prefix = sh_prefix;
        for (int i = tid; i < M; i += TPB) {
            unsigned long long key = cached ? s_cache[i]
                                   : (slow ? make_key(lg[i], (unsigned)i) : cand[i]);
            if ((key & pmask) == prefix)
                atomicAdd(&hist[(int)((key >> shift) & 255)], 1);
        }
        __syncthreads();
        int rem = sh_remaining;
        int h = hist[tid];
        int x = h;                      // suffix-scan within warp
        #pragma unroll
        for (int off = 1; off < 32; off <<= 1) {
            int y = __shfl_down_sync(0xffffffffu, x, off);
            if (lane + off < 32) x += y;
        }
        if (lane == 0) wtot[wid] = x;
        __syncthreads();
        int wsum = 0;
        #pragma unroll
        for (int w = 0; w < 8; w++) if (w > wid) wsum += wtot[w];
        int suffix = x + wsum;          // sum of hist[tid..255]
        if (suffix >= rem && (suffix - h) < rem) {   // unique chosen bin
            sh_prefix = prefix | ((unsigned long long)tid << shift);
            sh_remaining = rem - (suffix - h);
        }
        __syncthreads();
    }
    unsigned long long kth = sh_prefix;   // exact K-th largest key (keys unique)

    __shared__ unsigned long long win[KMAX];
    __shared__ int wc;
    if (tid == 0) wc = 0;
    __syncthreads();
    for (int i = tid; i < M; i += TPB) {
        unsigned long long key = cached ? s_cache[i]
                               : (slow ? make_key(lg[i], (unsigned)i) : cand[i]);
        if (key >= kth) {
            int p = atomicAdd(&wc, 1);
            if (p < KMAX) win[p] = key;
        }
    }
    __syncthreads();

    if (tid < K) {
        unsigned long long k0 = win[tid];
        int rank = 0;
        for (int j = 0; j < K; j++) rank += (win[j] > k0);
        float score = __uint_as_float((unsigned)(k0 >> 32));
        unsigned idx = ~(unsigned)(k0 & 0xffffffffu);
        int q = (int)(idx / (unsigned)C);
        int lbl = (int)(idx - (unsigned)q * (unsigned)C);
        float c = segs[((long long)b * Q + q) * 2 + 0];
        float w = segs[((long long)b * Q + q) * 2 + 1];
        float t = ts[b];
        int BK = B * K;
        int o = b * K + rank;
        out[o]                  = score;
        out[BK + o]             = (float)lbl;
        out[2 * BK + 2 * o]     = (c - 0.5f * w) * t;
        out[2 * BK + 2 * o + 1] = (c + 0.5f * w) * t;
        out[4 * BK + o]         = (float)q;
    }
    __syncthreads();
    if (tid == 0) { g_done[b] = 0; g_cnt[b] = 0; }   // reset for next graph replay
}

__global__ void __launch_bounds__(TPB)
k_main(const float* __restrict__ logits,
       const float* __restrict__ segs,
       const float* __restrict__ ts,
       float* __restrict__ out,
       int B, int Q, int C, int K, int per_cta, float thresh) {
    int b = blockIdx.y;
    int N = Q * C;
    int start = blockIdx.x * per_cta;
    int tid = threadIdx.x;

    __shared__ __align__(16) float4 s_pipe[DEPTH][TPB];   // 32 KB, per-thread columns
    __shared__ float    s_val[SBUF];
    __shared__ unsigned s_idx[SBUF];
    __shared__ int s_cnt;
    __shared__ int s_base;

    if (tid == 0) s_cnt = 0;
    __syncthreads();

    uint64_t pol = l2_keep_policy();

    auto push_hit = [&](float x, unsigned idx) {
        int pos = atomicAdd(&s_cnt, 1);
        if (pos < SBUF) {
            s_val[pos] = x;
            s_idx[pos] = idx;
        } else {                                   // smem overflow: direct global (rare)
            int p = atomicAdd(&g_cnt[b], 1);
            if (p < CAP) g_cand[b * CAP + p] = make_key(x, idx);
        }
    };

    if (start < N) {
        int count = min(per_cta, N - start);
        const float* base = logits + (long long)b * N + start;
        const float4* src = (const float4*)base;   // start is a multiple of 4 floats
        int n4 = count >> 2;
        int iters = (n4 + TPB - 1) / TPB;
        uint32_t myslot0 = smem_u32(&s_pipe[0][tid]);

        // prologue: fill per-thread ring (one commit group per slot; empty
        // groups complete immediately so numbering stays uniform)
        #pragma unroll
        for (int d = 0; d < DEPTH; d++) {
            int idx = d * TPB + tid;
            if (idx < n4) cp_async16(myslot0 + d * (TPB * 16), src + idx, pol);
            cp_commit();
        }

        for (int k = 0; k < iters; k++) {
            cp_wait_most();                       // group k complete -> slot k%DEPTH ready
            int s = k & (DEPTH - 1);
            int idx = k * TPB + tid;
            if (idx < n4) {
                float4 v = s_pipe[s][tid];
                if (max4(v) > thresh) {
                    unsigned i0 = (unsigned)(start + 4 * idx);
                    if (v.x > thresh) push_hit(v.x, i0);
                    if (v.y > thresh) push_hit(v.y, i0 + 1);
                    if (v.z > thresh) push_hit(v.z, i0 + 2);
                    if (v.w > thresh) push_hit(v.w, i0 + 3);
                }
            }
            int nidx = (k + DEPTH) * TPB + tid;   // refill consumed slot
            if (nidx < n4) cp_async16(myslot0 + s * (TPB * 16), src + nidx, pol);
            cp_commit();
        }
        cp_wait_all();                            // pipe smem idle before reuse

        // scalar tail (only if count % 4 != 0; never for this shape)
        int cnt4 = n4 << 2;
        int tail = count - cnt4;
        if (tid < tail) {
            float x = base[cnt4 + tid];
            if (x > thresh) push_hit(x, (unsigned)(start + cnt4 + tid));
        }
    }

    // ---- flush: convert staged (logit, idx) -> keys in global ----
    __syncthreads();
    int cnt = min(s_cnt, SBUF);
    if (tid == 0) s_base = atomicAdd(&g_cnt[b], cnt);
    __syncthreads();
    int bs = s_base;
    for (int i2 = tid; i2 < cnt; i2 += TPB) {
        int p = bs + i2;
        if (p < CAP) g_cand[b * CAP + p] = make_key(s_val[i2], s_idx[i2]);
    }

    // ---- arrival: last slice CTA of this batch performs the selection ----
    __threadfence();
    __syncthreads();
    __shared__ int is_last;
    if (tid == 0)
        is_last = (atomicAdd(&g_done[b], 1) == gridDim.x - 1);
    __syncthreads();
    if (is_last) {
        __threadfence();   // acquire: other CTAs' candidate stores visible
        do_select(logits + (long long)b * N, segs, ts, out,
                  (unsigned long long*)&s_pipe[0][0], b, B, Q, C, K, N);
    }
}

extern "C" void kernel_launch(void* const* d_in, const int* in_sizes, int n_in,
                              void* d_out, int out_size) {
    const float* logits = (const float*)d_in[0];   // [B, Q, C] f32
    const float* segs   = (const float*)d_in[1];   // [B, Q, 2] f32
    const float* ts     = (const float*)d_in[2];   // [B] f32

    int B = in_sizes[2];
    int N = in_sizes[0] / B;          // Q * C
    int Q = in_sizes[1] / (2 * B);
    int C = N / Q;
    int K = 100;
    if (K > N) K = N;

    int per_cta = (((N + SLICES - 1) / SLICES) + 3) & ~3;
    dim3 grid(SLICES, B);
    k_main<<<grid, TPB>>>(logits, segs, ts, (float*)d_out, B, Q, C, K, per_cta, 3.0f);
}

// round 16
// speedup vs baseline: 2.2935x; 1.0703x over previous
#include <cuda_runtime.h>
#include <math.h>
#include <stdint.h>

// B=64 batches, per batch N=Q*C=400000 fp32 logits.
// Output f32 concat: scores[B*K] | labels[B*K] | segments[B*K*2] | query_ids[B*K].
//
// Single fused kernel, grid (SLICES, B) = (8, 64) = 512 CTAs. This is the
// R15 winner (30.7us) unchanged except threshold 3.0 -> 3.2. R15 proved the
// hit path throttles load-issue cadence (BW rose 2787->3169 GB/s when the
// per-warp-iteration hit rate halved); this halves it again (16% -> 8.4%,
// E[candidates] ~275/batch, 10.5 sigma above K=100; the exact full-scan
// fallback keeps correctness unconditional for any input).
//
//  - collect: per-thread cp.async (LDGSTS) ring, DEPTH=8 x 16B slots, with
//    L2::evict_last hints. Hits staged in smem, bulk-flushed per batch.
//  - last-arriving slice CTA per batch: exact MSD radix-select over the
//    candidates (cached in the freed pipe smem), rank K winners, emit
//    outputs, reset counters for the next graph replay.
//  - exact fallback over the full batch if the candidate set is unusable.

#define MAXB    64
#define CAP     16384
#define SLICES  8
#define TPB     256
#define KMAX    128
#define SBUF    384
#define DEPTH   8
#define SELCACHE 4096     // u64 slots available in pipe smem (32KB)

__device__ unsigned long long g_cand[MAXB * CAP];
__device__ int g_cnt[MAXB];
__device__ int g_done[MAXB];

__device__ __forceinline__ unsigned long long make_key(float x, unsigned idx) {
    float s = 1.0f / (1.0f + expf(-x));   // sigmoid ordering == jax (rel_err 8e-9 verified)
    return ((unsigned long long)__float_as_uint(s) << 32) | (unsigned long long)(~idx);
}

__device__ __forceinline__ float max4(float4 v) {
    return fmaxf(fmaxf(v.x, v.y), fmaxf(v.z, v.w));
}

__device__ __forceinline__ uint32_t smem_u32(const void* p) {
    uint32_t a;
    asm("{ .reg .u64 t; cvta.to.shared.u64 t, %1; cvt.u32.u64 %0, t; }" : "=r"(a) : "l"(p));
    return a;
}

__device__ __forceinline__ uint64_t l2_keep_policy() {
    uint64_t p;
    asm("createpolicy.fractional.L2::evict_last.b64 %0, 1.0;" : "=l"(p));
    return p;
}

__device__ __forceinline__ void cp_async16(uint32_t dst, const float4* src, uint64_t pol) {
    asm volatile("cp.async.cg.shared.global.L2::cache_hint [%0], [%1], 16, %2;"
                 :: "r"(dst), "l"(src), "l"(pol) : "memory");
}
__device__ __forceinline__ void cp_commit() {
    asm volatile("cp.async.commit_group;" ::: "memory");
}
__device__ __forceinline__ void cp_wait_most() {       // allow DEPTH-1 outstanding
    asm volatile("cp.async.wait_group %0;" :: "n"(DEPTH - 1) : "memory");
}
__device__ __forceinline__ void cp_wait_all() {
    asm volatile("cp.async.wait_all;" ::: "memory");
}

// ---- exact top-K selection over candidates (or full logits on fallback) ----
__device__ void do_select(const float* __restrict__ lg,
                          const float* __restrict__ segs,
                          const float* __restrict__ ts,
                          float* __restrict__ out,
                          unsigned long long* s_cache,
                          int b, int B, int Q, int C, int K, int N) {
    int tid = threadIdx.x;
    int lane = tid & 31;
    int wid = tid >> 5;

    int cnt = g_cnt[b];
    bool slow = (cnt < K) || (cnt > CAP);
    int M = slow ? N : cnt;
    const unsigned long long* cand = g_cand + (long long)b * CAP;

    bool cached = (!slow) && (M <= SELCACHE);   // pipe smem is free now
    if (cached) {
        for (int i = tid; i < M; i += TPB) s_cache[i] = cand[i];
    }
    __shared__ int hist[256];
    __shared__ int wtot[8];
    __shared__ unsigned long long sh_prefix;
    __shared__ int sh_remaining;
    if (tid == 0) { sh_prefix = 0ULL; sh_remaining = K; }
    __syncthreads();

    for (int d = 7; d >= 0; --d) {
        hist[tid] = 0;
        __syncthreads();
        int shift = d * 8;
        unsigned long long pmask = (d == 7) ? 0ULL : (~0ULL << (shift + 8));
        unsigned long long prefix = sh_prefix;
        for (int i = tid; i < M; i += TPB) {
            unsigned long long key = cached ? s_cache[i]
                                   : (slow ? make_key(lg[i], (unsigned)i) : cand[i]);
            if ((key & pmask) == prefix)
                atomicAdd(&hist[(int)((key >> shift) & 255)], 1);
        }
        __syncthreads();
        int rem = sh_remaining;
        int h = hist[tid];
        int x = h;                      // suffix-scan within warp
        #pragma unroll
        for (int off = 1; off < 32; off <<= 1) {
            int y = __shfl_down_sync(0xffffffffu, x, off);
            if (lane + off < 32) x += y;
        }
        if (lane == 0) wtot[wid] = x;
        __syncthreads();
        int wsum = 0;
        #pragma unroll
        for (int w = 0; w < 8; w++) if (w > wid) wsum += wtot[w];
        int suffix = x + wsum;          // sum of hist[tid..255]
        if (suffix >= rem && (suffix - h) < rem) {   // unique chosen bin
            sh_prefix = prefix | ((unsigned long long)tid << shift);
            sh_remaining = rem - (suffix - h);
        }
        __syncthreads();
    }
    unsigned long long kth = sh_prefix;   // exact K-th largest key (keys unique)

    __shared__ unsigned long long win[KMAX];
    __shared__ int wc;
    if (tid == 0) wc = 0;
    __syncthreads();
    for (int i = tid; i < M; i += TPB) {
        unsigned long long key = cached ? s_cache[i]
                               : (slow ? make_key(lg[i], (unsigned)i) : cand[i]);
        if (key >= kth) {
            int p = atomicAdd(&wc, 1);
            if (p < KMAX) win[p] = key;
        }
    }
    __syncthreads();

    if (tid < K) {
        unsigned long long k0 = win[tid];
        int rank = 0;
        for (int j = 0; j < K; j++) rank += (win[j] > k0);
        float score = __uint_as_float((unsigned)(k0 >> 32));
        unsigned idx = ~(unsigned)(k0 & 0xffffffffu);
        int q = (int)(idx / (unsigned)C);
        int lbl = (int)(idx - (unsigned)q * (unsigned)C);
        float c = segs[((long long)b * Q + q) * 2 + 0];
        float w = segs[((long long)b * Q + q) * 2 + 1];
        float t = ts[b];
        int BK = B * K;
        int o = b * K + rank;
        out[o]                  = score;
        out[BK + o]             = (float)lbl;
        out[2 * BK + 2 * o]     = (c - 0.5f * w) * t;
        out[2 * BK + 2 * o + 1] = (c + 0.5f * w) * t;
        out[4 * BK + o]         = (float)q;
    }
    __syncthreads();
    if (tid == 0) { g_done[b] = 0; g_cnt[b] = 0; }   // reset for next graph replay
}

__global__ void __launch_bounds__(TPB)
k_main(const float* __restrict__ logits,
       const float* __restrict__ segs,
       const float* __restrict__ ts,
       float* __restrict__ out,
       int B, int Q, int C, int K, int per_cta, float thresh) {
    int b = blockIdx.y;
    int N = Q * C;
    int start = blockIdx.x * per_cta;
    int tid = threadIdx.x;

    __shared__ __align__(16) float4 s_pipe[DEPTH][TPB];   // 32 KB, per-thread columns
    __shared__ float    s_val[SBUF];
    __shared__ unsigned s_idx[SBUF];
    __shared__ int s_cnt;
    __shared__ int s_base;

    if (tid == 0) s_cnt = 0;
    __syncthreads();

    uint64_t pol = l2_keep_policy();

    auto push_hit = [&](float x, unsigned idx) {
        int pos = atomicAdd(&s_cnt, 1);
        if (pos < SBUF) {
            s_val[pos] = x;
            s_idx[pos] = idx;
        } else {                                   // smem overflow: direct global (rare)
            int p = atomicAdd(&g_cnt[b], 1);
            if (p < CAP) g_cand[b * CAP + p] = make_key(x, idx);
        }
    };

    if (start < N) {
        int count = min(per_cta, N - start);
        const float* base = logits + (long long)b * N + start;
        const float4* src = (const float4*)base;   // start is a multiple of 4 floats
        int n4 = count >> 2;
        int iters = (n4 + TPB - 1) / TPB;
        uint32_t myslot0 = smem_u32(&s_pipe[0][tid]);

        // prologue: fill per-thread ring (one commit group per slot; empty
        // groups complete immediately so numbering stays uniform)
        #pragma unroll
        for (int d = 0; d < DEPTH; d++) {
            int idx = d * TPB + tid;
            if (idx < n4) cp_async16(myslot0 + d * (TPB * 16), src + idx, pol);
            cp_commit();
        }

        for (int k = 0; k < iters; k++) {
            cp_wait_most();                       // group k complete -> slot k%DEPTH ready
            int s = k & (DEPTH - 1);
            int idx = k * TPB + tid;
            if (idx < n4) {
                float4 v = s_pipe[s][tid];
                if (max4(v) > thresh) {
                    unsigned i0 = (unsigned)(start + 4 * idx);
                    if (v.x > thresh) push_hit(v.x, i0);
                    if (v.y > thresh) push_hit(v.y, i0 + 1);
                    if (v.z > thresh) push_hit(v.z, i0 + 2);
                    if (v.w > thresh) push_hit(v.w, i0 + 3);
                }
            }
            int nidx = (k + DEPTH) * TPB + tid;   // refill consumed slot
            if (nidx < n4) cp_async16(myslot0 + s * (TPB * 16), src + nidx, pol);
            cp_commit();
        }
        cp_wait_all();                            // pipe smem idle before reuse

        // scalar tail (only if count % 4 != 0; never for this shape)
        int cnt4 = n4 << 2;
        int tail = count - cnt4;
        if (tid < tail) {
            float x = base[cnt4 + tid];
            if (x > thresh) push_hit(x, (unsigned)(start + cnt4 + tid));
        }
    }

    // ---- flush: convert staged (logit, idx) -> keys in global ----
    __syncthreads();
    int cnt = min(s_cnt, SBUF);
    if (tid == 0) s_base = atomicAdd(&g_cnt[b], cnt);
    __syncthreads();
    int bs = s_base;
    for (int i2 = tid; i2 < cnt; i2 += TPB) {
        int p = bs + i2;
        if (p < CAP) g_cand[b * CAP + p] = make_key(s_val[i2], s_idx[i2]);
    }

    // ---- arrival: last slice CTA of this batch performs the selection ----
    __threadfence();
    __syncthreads();
    __shared__ int is_last;
    if (tid == 0)
        is_last = (atomicAdd(&g_done[b], 1) == gridDim.x - 1);
    __syncthreads();
    if (is_last) {
        __threadfence();   // acquire: other CTAs' candidate stores visible
        do_select(logits + (long long)b * N, segs, ts, out,
                  (unsigned long long*)&s_pipe[0][0], b, B, Q, C, K, N);
    }
}

extern "C" void kernel_launch(void* const* d_in, const int* in_sizes, int n_in,
                              void* d_out, int out_size) {
    const float* logits = (const float*)d_in[0];   // [B, Q, C] f32
    const float* segs   = (const float*)d_in[1];   // [B, Q, 2] f32
    const float* ts     = (const float*)d_in[2];   // [B] f32

    int B = in_sizes[2];
    int N = in_sizes[0] / B;          // Q * C
    int Q = in_sizes[1] / (2 * B);
    int C = N / Q;
    int K = 100;
    if (K > N) K = N;

    int per_cta = (((N + SLICES - 1) / SLICES) + 3) & ~3;
    dim3 grid(SLICES, B);
    k_main<<<grid, TPB>>>(logits, segs, ts, (float*)d_out, B, Q, C, K, per_cta, 3.2f);
}

// round 17
// speedup vs baseline: 2.3326x; 1.0170x over previous
#include <cuda_runtime.h>
#include <math.h>
#include <stdint.h>

// B=64 batches, per batch N=Q*C=400000 fp32 logits.
// Output f32 concat: scores[B*K] | labels[B*K] | segments[B*K*2] | query_ids[B*K].
//
// Single fused kernel, grid (SLICES, B) = (8, 64) = 512 CTAs. This is the
// R16 winner (28.7us) unchanged except threshold 3.2 -> 3.3. R15/R16 proved
// the hit path throttles load-issue cadence (BW 2787->3169->3321 GB/s as the
// hit rate halved twice); this trims it further (warp-iter hit rate 8.4% ->
// 5.9%, E[candidates] ~193/batch, worst-of-64 ~162 = 6.7 sigma above K=100;
// the exact full-scan fallback keeps correctness unconditional).
//
//  - collect: per-thread cp.async (LDGSTS) ring, DEPTH=8 x 16B slots, with
//    L2::evict_last hints. Hits staged in smem, bulk-flushed per batch.
//  - last-arriving slice CTA per batch: exact MSD radix-select over the
//    candidates (cached in the freed pipe smem), rank K winners, emit
//    outputs, reset counters for the next graph replay.
//  - exact fallback over the full batch if the candidate set is unusable.

#define MAXB    64
#define CAP     16384
#define SLICES  8
#define TPB     256
#define KMAX    128
#define SBUF    384
#define DEPTH   8
#define SELCACHE 4096     // u64 slots available in pipe smem (32KB)

__device__ unsigned long long g_cand[MAXB * CAP];
__device__ int g_cnt[MAXB];
__device__ int g_done[MAXB];

__device__ __forceinline__ unsigned long long make_key(float x, unsigned idx) {
    float s = 1.0f / (1.0f + expf(-x));   // sigmoid ordering == jax (rel_err 8e-9 verified)
    return ((unsigned long long)__float_as_uint(s) << 32) | (unsigned long long)(~idx);
}

__device__ __forceinline__ float max4(float4 v) {
    return fmaxf(fmaxf(v.x, v.y), fmaxf(v.z, v.w));
}

__device__ __forceinline__ uint32_t smem_u32(const void* p) {
    uint32_t a;
    asm("{ .reg .u64 t; cvta.to.shared.u64 t, %1; cvt.u32.u64 %0, t; }" : "=r"(a) : "l"(p));
    return a;
}

__device__ __forceinline__ uint64_t l2_keep_policy() {
    uint64_t p;
    asm("createpolicy.fractional.L2::evict_last.b64 %0, 1.0;" : "=l"(p));
    return p;
}

__device__ __forceinline__ void cp_async16(uint32_t dst, const float4* src, uint64_t pol) {
    asm volatile("cp.async.cg.shared.global.L2::cache_hint [%0], [%1], 16, %2;"
                 :: "r"(dst), "l"(src), "l"(pol) : "memory");
}
__device__ __forceinline__ void cp_commit() {
    asm volatile("cp.async.commit_group;" ::: "memory");
}
__device__ __forceinline__ void cp_wait_most() {       // allow DEPTH-1 outstanding
    asm volatile("cp.async.wait_group %0;" :: "n"(DEPTH - 1) : "memory");
}
__device__ __forceinline__ void cp_wait_all() {
    asm volatile("cp.async.wait_all;" ::: "memory");
}

// ---- exact top-K selection over candidates (or full logits on fallback) ----
__device__ void do_select(const float* __restrict__ lg,
                          const float* __restrict__ segs,
                          const float* __restrict__ ts,
                          float* __restrict__ out,
                          unsigned long long* s_cache,
                          int b, int B, int Q, int C, int K, int N) {
    int tid = threadIdx.x;
    int lane = tid & 31;
    int wid = tid >> 5;

    int cnt = g_cnt[b];
    bool slow = (cnt < K) || (cnt > CAP);
    int M = slow ? N : cnt;
    const unsigned long long* cand = g_cand + (long long)b * CAP;

    bool cached = (!slow) && (M <= SELCACHE);   // pipe smem is free now
    if (cached) {
        for (int i = tid; i < M; i += TPB) s_cache[i] = cand[i];
    }
    __shared__ int hist[256];
    __shared__ int wtot[8];
    __shared__ unsigned long long sh_prefix;
    __shared__ int sh_remaining;
    if (tid == 0) { sh_prefix = 0ULL; sh_remaining = K; }
    __syncthreads();

    for (int d = 7; d >= 0; --d) {
        hist[tid] = 0;
        __syncthreads();
        int shift = d * 8;
        unsigned long long pmask = (d == 7) ? 0ULL : (~0ULL << (shift + 8));
        unsigned long long prefix = sh_prefix;
        for (int i = tid; i < M; i += TPB) {
            unsigned long long key = cached ? s_cache[i]
                                   : (slow ? make_key(lg[i], (unsigned)i) : cand[i]);
            if ((key & pmask) == prefix)
                atomicAdd(&hist[(int)((key >> shift) & 255)], 1);
        }
        __syncthreads();
        int rem = sh_remaining;
        int h = hist[tid];
        int x = h;                      // suffix-scan within warp
        #pragma unroll
        for (int off = 1; off < 32; off <<= 1) {
            int y = __shfl_down_sync(0xffffffffu, x, off);
            if (lane + off < 32) x += y;
        }
        if (lane == 0) wtot[wid] = x;
        __syncthreads();
        int wsum = 0;
        #pragma unroll
        for (int w = 0; w < 8; w++) if (w > wid) wsum += wtot[w];
        int suffix = x + wsum;          // sum of hist[tid..255]
        if (suffix >= rem && (suffix - h) < rem) {   // unique chosen bin
            sh_prefix = prefix | ((unsigned long long)tid << shift);
            sh_remaining = rem - (suffix - h);
        }
        __syncthreads();
    }
    unsigned long long kth = sh_prefix;   // exact K-th largest key (keys unique)

    __shared__ unsigned long long win[KMAX];
    __shared__ int wc;
    if (tid == 0) wc = 0;
    __syncthreads();
    for (int i = tid; i < M; i += TPB) {
        unsigned long long key = cached ? s_cache[i]
                               : (slow ? make_key(lg[i], (unsigned)i) : cand[i]);
        if (key >= kth) {
            int p = atomicAdd(&wc, 1);
            if (p < KMAX) win[p] = key;
        }
    }
    __syncthreads();

    if (tid < K) {
        unsigned long long k0 = win[tid];
        int rank = 0;
        for (int j = 0; j < K; j++) rank += (win[j] > k0);
        float score = __uint_as_float((unsigned)(k0 >> 32));
        unsigned idx = ~(unsigned)(k0 & 0xffffffffu);
        int q = (int)(idx / (unsigned)C);
        int lbl = (int)(idx - (unsigned)q * (unsigned)C);
        float c = segs[((long long)b * Q + q) * 2 + 0];
        float w = segs[((long long)b * Q + q) * 2 + 1];
        float t = ts[b];
        int BK = B * K;
        int o = b * K + rank;
        out[o]                  = score;
        out[BK + o]             = (float)lbl;
        out[2 * BK + 2 * o]     = (c - 0.5f * w) * t;
        out[2 * BK + 2 * o + 1] = (c + 0.5f * w) * t;
        out[4 * BK + o]         = (float)q;
    }
    __syncthreads();
    if (tid == 0) { g_done[b] = 0; g_cnt[b] = 0; }   // reset for next graph replay
}

__global__ void __launch_bounds__(TPB)
k_main(const float* __restrict__ logits,
       const float* __restrict__ segs,
       const float* __restrict__ ts,
       float* __restrict__ out,
       int B, int Q, int C, int K, int per_cta, float thresh) {
    int b = blockIdx.y;
    int N = Q * C;
    int start = blockIdx.x * per_cta;
    int tid = threadIdx.x;

    __shared__ __align__(16) float4 s_pipe[DEPTH][TPB];   // 32 KB, per-thread columns
    __shared__ float    s_val[SBUF];
    __shared__ unsigned s_idx[SBUF];
    __shared__ int s_cnt;
    __shared__ int s_base;

    if (tid == 0) s_cnt = 0;
    __syncthreads();

    uint64_t pol = l2_keep_policy();

    auto push_hit = [&](float x, unsigned idx) {
        int pos = atomicAdd(&s_cnt, 1);
        if (pos < SBUF) {
            s_val[pos] = x;
            s_idx[pos] = idx;
        } else {                                   // smem overflow: direct global (rare)
            int p = atomicAdd(&g_cnt[b], 1);
            if (p < CAP) g_cand[b * CAP + p] = make_key(x, idx);
        }
    };

    if (start < N) {
        int count = min(per_cta, N - start);
        const float* base = logits + (long long)b * N + start;
        const float4* src = (const float4*)base;   // start is a multiple of 4 floats
        int n4 = count >> 2;
        int iters = (n4 + TPB - 1) / TPB;
        uint32_t myslot0 = smem_u32(&s_pipe[0][tid]);

        // prologue: fill per-thread ring (one commit group per slot; empty
        // groups complete immediately so numbering stays uniform)
        #pragma unroll
        for (int d = 0; d < DEPTH; d++) {
            int idx = d * TPB + tid;
            if (idx < n4) cp_async16(myslot0 + d * (TPB * 16), src + idx, pol);
            cp_commit();
        }

        for (int k = 0; k < iters; k++) {
            cp_wait_most();                       // group k complete -> slot k%DEPTH ready
            int s = k & (DEPTH - 1);
            int idx = k * TPB + tid;
            if (idx < n4) {
                float4 v = s_pipe[s][tid];
                if (max4(v) > thresh) {
                    unsigned i0 = (unsigned)(start + 4 * idx);
                    if (v.x > thresh) push_hit(v.x, i0);
                    if (v.y > thresh) push_hit(v.y, i0 + 1);
                    if (v.z > thresh) push_hit(v.z, i0 + 2);
                    if (v.w > thresh) push_hit(v.w, i0 + 3);
                }
            }
            int nidx = (k + DEPTH) * TPB + tid;   // refill consumed slot
            if (nidx < n4) cp_async16(myslot0 + s * (TPB * 16), src + nidx, pol);
            cp_commit();
        }
        cp_wait_all();                            // pipe smem idle before reuse

        // scalar tail (only if count % 4 != 0; never for this shape)
        int cnt4 = n4 << 2;
        int tail = count - cnt4;
        if (tid < tail) {
            float x = base[cnt4 + tid];
            if (x > thresh) push_hit(x, (unsigned)(start + cnt4 + tid));
        }
    }

    // ---- flush: convert staged (logit, idx) -> keys in global ----
    __syncthreads();
    int cnt = min(s_cnt, SBUF);
    if (tid == 0) s_base = atomicAdd(&g_cnt[b], cnt);
    __syncthreads();
    int bs = s_base;
    for (int i2 = tid; i2 < cnt; i2 += TPB) {
        int p = bs + i2;
        if (p < CAP) g_cand[b * CAP + p] = make_key(s_val[i2], s_idx[i2]);
    }

    // ---- arrival: last slice CTA of this batch performs the selection ----
    __threadfence();
    __syncthreads();
    __shared__ int is_last;
    if (tid == 0)
        is_last = (atomicAdd(&g_done[b], 1) == gridDim.x - 1);
    __syncthreads();
    if (is_last) {
        __threadfence();   // acquire: other CTAs' candidate stores visible
        do_select(logits + (long long)b * N, segs, ts, out,
                  (unsigned long long*)&s_pipe[0][0], b, B, Q, C, K, N);
    }
}

extern "C" void kernel_launch(void* const* d_in, const int* in_sizes, int n_in,
                              void* d_out, int out_size) {
    const float* logits = (const float*)d_in[0];   // [B, Q, C] f32
    const float* segs   = (const float*)d_in[1];   // [B, Q, 2] f32
    const float* ts     = (const float*)d_in[2];   // [B] f32

    int B = in_sizes[2];
    int N = in_sizes[0] / B;          // Q * C
    int Q = in_sizes[1] / (2 * B);
    int C = N / Q;
    int K = 100;
    if (K > N) K = N;

    int per_cta = (((N + SLICES - 1) / SLICES) + 3) & ~3;
    dim3 grid(SLICES, B);
    k_main<<<grid, TPB>>>(logits, segs, ts, (float*)d_out, B, Q, C, K, per_cta, 3.3f);
}